// round 4
// baseline (speedup 1.0000x reference)
#include <cuda_runtime.h>
#include <math.h>

constexpr int BB = 2;
constexpr int NN = 2048;
constexpr int CC = 1024;
constexpr int HH = 8;
constexpr int DH = 128;
constexpr int MALL = BB * NN;  // 4096

__device__ float g_q[(size_t)MALL * CC];
__device__ float g_k[(size_t)MALL * CC];
__device__ float g_v[(size_t)MALL * CC];
__device__ float g_att[(size_t)MALL * CC];

// ---------------------------------------------------------------------------
// tf32 helpers
// ---------------------------------------------------------------------------
__device__ __forceinline__ float f2tf(float x) {
  unsigned u;
  asm("cvt.rna.tf32.f32 %0, %1;" : "=r"(u) : "f"(x));
  return __uint_as_float(u);
}
__device__ __forceinline__ unsigned fu(float x) { return __float_as_uint(x); }

// D += A(16x8) * B(8x8), tf32, row.col
__device__ __forceinline__ void mma8(float* c, const unsigned* a, unsigned b0,
                                     unsigned b1) {
  asm volatile(
      "mma.sync.aligned.m16n8k8.row.col.f32.tf32.tf32.f32 "
      "{%0,%1,%2,%3}, {%4,%5,%6,%7}, {%8,%9}, {%0,%1,%2,%3};"
      : "+f"(c[0]), "+f"(c[1]), "+f"(c[2]), "+f"(c[3])
      : "r"(a[0]), "r"(a[1]), "r"(a[2]), "r"(a[3]), "r"(b0), "r"(b1));
}

// ---------------------------------------------------------------------------
// GEMM: C[4096,1024] = A @ B + bias, tf32 tensor-core, 128x128x32 tiles.
// (unchanged from round 3)
// ---------------------------------------------------------------------------
__global__ __launch_bounds__(256) void sgemm_tf32_kernel(
    const float* __restrict__ A, const float* __restrict__ B,
    const float* __restrict__ bias, float* __restrict__ C) {
  constexpr int K = 1024, N = 1024;
  __shared__ float As[128][36];
  __shared__ float Bs[32][136];

  const int tid = threadIdx.x;
  const int warp = tid >> 5, lane = tid & 31;
  const int g = lane >> 2, t = lane & 3;
  const int wm = warp & 3, wn = warp >> 2;
  const int bx = blockIdx.x, by = blockIdx.y;

  const int ar = tid >> 3, ac = (tid & 7) * 4;
  const int bkr = tid >> 5, bc = (tid & 31) * 4;

  float acc[2][8][4];
#pragma unroll
  for (int mt = 0; mt < 2; mt++)
#pragma unroll
    for (int nt = 0; nt < 8; nt++)
#pragma unroll
      for (int i = 0; i < 4; i++) acc[mt][nt][i] = 0.f;

  float4 pa[4], pb[4];
#pragma unroll
  for (int i = 0; i < 4; i++) {
    pa[i] = *(const float4*)(A + (size_t)(by * 128 + ar + 32 * i) * K + ac);
    pb[i] = *(const float4*)(B + (size_t)(bkr + 8 * i) * N + bx * 128 + bc);
  }

  for (int k0 = 0; k0 < K; k0 += 32) {
#pragma unroll
    for (int i = 0; i < 4; i++) {
      As[ar + 32 * i][ac + 0] = f2tf(pa[i].x);
      As[ar + 32 * i][ac + 1] = f2tf(pa[i].y);
      As[ar + 32 * i][ac + 2] = f2tf(pa[i].z);
      As[ar + 32 * i][ac + 3] = f2tf(pa[i].w);
      Bs[bkr + 8 * i][bc + 0] = f2tf(pb[i].x);
      Bs[bkr + 8 * i][bc + 1] = f2tf(pb[i].y);
      Bs[bkr + 8 * i][bc + 2] = f2tf(pb[i].z);
      Bs[bkr + 8 * i][bc + 3] = f2tf(pb[i].w);
    }
    __syncthreads();

    if (k0 + 32 < K) {
#pragma unroll
      for (int i = 0; i < 4; i++) {
        pa[i] = *(const float4*)(A + (size_t)(by * 128 + ar + 32 * i) * K +
                                 k0 + 32 + ac);
        pb[i] = *(const float4*)(B + (size_t)(k0 + 32 + bkr + 8 * i) * N +
                                 bx * 128 + bc);
      }
    }

#pragma unroll
    for (int ks = 0; ks < 4; ks++) {
      const int kk = ks * 8;
      unsigned afr[2][4];
#pragma unroll
      for (int mt = 0; mt < 2; mt++) {
        const int rr = wm * 32 + mt * 16;
        afr[mt][0] = fu(As[rr + g][kk + t]);
        afr[mt][1] = fu(As[rr + g + 8][kk + t]);
        afr[mt][2] = fu(As[rr + g][kk + t + 4]);
        afr[mt][3] = fu(As[rr + g + 8][kk + t + 4]);
      }
#pragma unroll
      for (int nt = 0; nt < 8; nt++) {
        const int cc = wn * 64 + nt * 8 + g;
        unsigned b0 = fu(Bs[kk + t][cc]);
        unsigned b1 = fu(Bs[kk + t + 4][cc]);
        mma8(acc[0][nt], afr[0], b0, b1);
        mma8(acc[1][nt], afr[1], b0, b1);
      }
    }
    __syncthreads();
  }

#pragma unroll
  for (int mt = 0; mt < 2; mt++) {
    const int r0 = by * 128 + wm * 32 + mt * 16 + g;
#pragma unroll
    for (int nt = 0; nt < 8; nt++) {
      const int c = bx * 128 + wn * 64 + nt * 8 + 2 * t;
      const float bx0 = bias[c], bx1 = bias[c + 1];
      float2 o0 = {acc[mt][nt][0] + bx0, acc[mt][nt][1] + bx1};
      float2 o1 = {acc[mt][nt][2] + bx0, acc[mt][nt][3] + bx1};
      *(float2*)(C + (size_t)r0 * N + c) = o0;
      *(float2*)(C + (size_t)(r0 + 8) * N + c) = o1;
    }
  }
}

// ---------------------------------------------------------------------------
// Flash attention, tf32 tensor-core. Br=128, Bc=64, 512 threads / 16 warps.
// smem: sQ[128][132], sK[64][132], sV[64][132], sS[128][68], sM/L/A[128]
// Stride 132 (== 4 mod 32): A-frag bank = 4g+t, B-frag bank = 4t+g, both
// conflict-free; float4-aligned (132*4B = 33*16B).
// ---------------------------------------------------------------------------
constexpr int SQ_STR = 132;
constexpr int SS_STR = 68;
constexpr int OFF_Q = 0;
constexpr int OFF_K = OFF_Q + 128 * SQ_STR;
constexpr int OFF_V = OFF_K + 64 * SQ_STR;
constexpr int OFF_S = OFF_V + 64 * SQ_STR;
constexpr int OFF_M = OFF_S + 128 * SS_STR;
constexpr int OFF_L = OFF_M + 128;
constexpr int OFF_A = OFF_L + 128;
constexpr int ATT_SMEM_BYTES = (OFF_A + 128) * 4;  // 171,520 B

__global__ __launch_bounds__(512) void attn_tf32_kernel(
    const float* __restrict__ Q, const float* __restrict__ K,
    const float* __restrict__ V, float* __restrict__ O) {
  extern __shared__ float sm[];
  const int tid = threadIdx.x;
  const int warp = tid >> 5, lane = tid & 31;
  const int g = lane >> 2, t = lane & 3;
  const int wm = warp & 7;    // 8 row-strips of 16
  const int wn = warp >> 3;   // 2 col-strips
  const int bh = blockIdx.y;
  const int b = bh >> 3, h = bh & 7;
  const int n0 = blockIdx.x * 128;

  const float* Qb = Q + (size_t)b * NN * CC + (size_t)h * DH;
  const float* Kb = K + (size_t)b * NN * CC + (size_t)h * DH;
  const float* Vb = V + (size_t)b * NN * CC + (size_t)h * DH;
  const float scale = 0.08838834764831845f;  // 1/sqrt(128)

  // Q tile (scaled, tf32-rounded): 4096 float4s over 512 threads
#pragma unroll
  for (int i = 0; i < 8; i++) {
    int l = tid + 512 * i;
    int r = l >> 5, d4 = (l & 31) << 2;
    float4 q = *(const float4*)(Qb + (size_t)(n0 + r) * CC + d4);
    sm[OFF_Q + r * SQ_STR + d4 + 0] = f2tf(q.x * scale);
    sm[OFF_Q + r * SQ_STR + d4 + 1] = f2tf(q.y * scale);
    sm[OFF_Q + r * SQ_STR + d4 + 2] = f2tf(q.z * scale);
    sm[OFF_Q + r * SQ_STR + d4 + 3] = f2tf(q.w * scale);
  }
  if (tid < 128) {
    sm[OFF_M + tid] = -INFINITY;
    sm[OFF_L + tid] = 0.f;
  }

  float oacc[8][4];
#pragma unroll
  for (int nt = 0; nt < 8; nt++)
#pragma unroll
    for (int i = 0; i < 4; i++) oacc[nt][i] = 0.f;
  __syncthreads();

  for (int j0 = 0; j0 < NN; j0 += 64) {
    // K/V chunk load (tf32-rounded): 2048 float4s each over 512 threads
#pragma unroll
    for (int i = 0; i < 4; i++) {
      int l = tid + 512 * i;
      int r = l >> 5, d4 = (l & 31) << 2;
      float4 kv = *(const float4*)(Kb + (size_t)(j0 + r) * CC + d4);
      float4 vv = *(const float4*)(Vb + (size_t)(j0 + r) * CC + d4);
      sm[OFF_K + r * SQ_STR + d4 + 0] = f2tf(kv.x);
      sm[OFF_K + r * SQ_STR + d4 + 1] = f2tf(kv.y);
      sm[OFF_K + r * SQ_STR + d4 + 2] = f2tf(kv.z);
      sm[OFF_K + r * SQ_STR + d4 + 3] = f2tf(kv.w);
      sm[OFF_V + r * SQ_STR + d4 + 0] = f2tf(vv.x);
      sm[OFF_V + r * SQ_STR + d4 + 1] = f2tf(vv.y);
      sm[OFF_V + r * SQ_STR + d4 + 2] = f2tf(vv.z);
      sm[OFF_V + r * SQ_STR + d4 + 3] = f2tf(vv.w);
    }
    __syncthreads();

    // ---- S = Qs @ Ks^T: warp tile 16 rows x 32 cols, 16 k-steps ----
    float sacc[4][4];
#pragma unroll
    for (int nt = 0; nt < 4; nt++)
#pragma unroll
      for (int i = 0; i < 4; i++) sacc[nt][i] = 0.f;

    const int rr = wm * 16;
#pragma unroll
    for (int ks = 0; ks < 16; ks++) {
      const int kk = ks * 8;
      unsigned afr[4];
      afr[0] = fu(sm[OFF_Q + (rr + g) * SQ_STR + kk + t]);
      afr[1] = fu(sm[OFF_Q + (rr + g + 8) * SQ_STR + kk + t]);
      afr[2] = fu(sm[OFF_Q + (rr + g) * SQ_STR + kk + t + 4]);
      afr[3] = fu(sm[OFF_Q + (rr + g + 8) * SQ_STR + kk + t + 4]);
#pragma unroll
      for (int nt = 0; nt < 4; nt++) {
        const int cc = wn * 32 + nt * 8 + g;
        unsigned b0 = fu(sm[OFF_K + cc * SQ_STR + kk + t]);
        unsigned b1 = fu(sm[OFF_K + cc * SQ_STR + kk + t + 4]);
        mma8(sacc[nt], afr, b0, b1);
      }
    }
    {
      const int r0 = rr + g;
#pragma unroll
      for (int nt = 0; nt < 4; nt++) {
        const int c = wn * 32 + nt * 8 + 2 * t;
        *(float2*)&sm[OFF_S + r0 * SS_STR + c] =
            make_float2(sacc[nt][0], sacc[nt][1]);
        *(float2*)&sm[OFF_S + (r0 + 8) * SS_STR + c] =
            make_float2(sacc[nt][2], sacc[nt][3]);
      }
    }
    __syncthreads();

    // ---- online softmax: 4 threads per row, 16 entries each ----
    {
      int r = tid >> 2;
      int c0 = (tid & 3) << 4;
      float* row = &sm[OFF_S + r * SS_STR + c0];
      float mx = row[0];
#pragma unroll
      for (int n = 1; n < 16; n++) mx = fmaxf(mx, row[n]);
      mx = fmaxf(mx, __shfl_xor_sync(0xffffffffu, mx, 1));
      mx = fmaxf(mx, __shfl_xor_sync(0xffffffffu, mx, 2));
      float mo = sm[OFF_M + r];
      float mn = fmaxf(mo, mx);
      float al = __expf(mo - mn);
      float s = 0.f;
#pragma unroll
      for (int n = 0; n < 16; n++) {
        float p = f2tf(__expf(row[n] - mn));  // round so L matches PV inputs
        row[n] = p;
        s += p;
      }
      s += __shfl_xor_sync(0xffffffffu, s, 1);
      s += __shfl_xor_sync(0xffffffffu, s, 2);
      if ((tid & 3) == 0) {
        sm[OFF_M + r] = mn;
        sm[OFF_A + r] = al;
        sm[OFF_L + r] = sm[OFF_L + r] * al + s;
      }
    }
    __syncthreads();

    // ---- PV: O += P @ V: warp tile 16 rows x 64 cols, 8 k-steps ----
    {
      const float al0 = sm[OFF_A + rr + g];
      const float al1 = sm[OFF_A + rr + g + 8];
#pragma unroll
      for (int nt = 0; nt < 8; nt++) {
        oacc[nt][0] *= al0;
        oacc[nt][1] *= al0;
        oacc[nt][2] *= al1;
        oacc[nt][3] *= al1;
      }

#pragma unroll
      for (int ks = 0; ks < 8; ks++) {
        const int kk = ks * 8;
        unsigned afr[4];
        afr[0] = fu(sm[OFF_S + (rr + g) * SS_STR + kk + t]);
        afr[1] = fu(sm[OFF_S + (rr + g + 8) * SS_STR + kk + t]);
        afr[2] = fu(sm[OFF_S + (rr + g) * SS_STR + kk + t + 4]);
        afr[3] = fu(sm[OFF_S + (rr + g + 8) * SS_STR + kk + t + 4]);
#pragma unroll
        for (int nt = 0; nt < 8; nt++) {
          const int cc = wn * 64 + nt * 8 + g;
          unsigned b0 = fu(sm[OFF_V + (kk + t) * SQ_STR + cc]);
          unsigned b1 = fu(sm[OFF_V + (kk + t + 4) * SQ_STR + cc]);
          mma8(oacc[nt], afr, b0, b1);
        }
      }
    }
    __syncthreads();
  }

  // ---- epilogue ----
  float* Ob = O + (size_t)b * NN * CC + (size_t)h * DH;
  {
    const int r0 = wm * 16 + g;
    const float inv0 = 1.0f / sm[OFF_L + r0];
    const float inv1 = 1.0f / sm[OFF_L + r0 + 8];
#pragma unroll
    for (int nt = 0; nt < 8; nt++) {
      const int c = wn * 64 + nt * 8 + 2 * t;
      *(float2*)(Ob + (size_t)(n0 + r0) * CC + c) =
          make_float2(oacc[nt][0] * inv0, oacc[nt][1] * inv0);
      *(float2*)(Ob + (size_t)(n0 + r0 + 8) * CC + c) =
          make_float2(oacc[nt][2] * inv1, oacc[nt][3] * inv1);
    }
  }
}

// ---------------------------------------------------------------------------
extern "C" void kernel_launch(void* const* d_in, const int* in_sizes, int n_in,
                              void* d_out, int out_size) {
  const float* xq = (const float*)d_in[0];
  const float* xkv = (const float*)d_in[1];
  const float* Wq = (const float*)d_in[2];
  const float* bq = (const float*)d_in[3];
  const float* Wk = (const float*)d_in[4];
  const float* bk = (const float*)d_in[5];
  const float* Wv = (const float*)d_in[6];
  const float* bv = (const float*)d_in[7];
  const float* Wo = (const float*)d_in[8];
  const float* bo = (const float*)d_in[9];
  float* out = (float*)d_out;

  float *q, *k, *v, *att;
  cudaGetSymbolAddress((void**)&q, g_q);
  cudaGetSymbolAddress((void**)&k, g_k);
  cudaGetSymbolAddress((void**)&v, g_v);
  cudaGetSymbolAddress((void**)&att, g_att);

  cudaFuncSetAttribute(attn_tf32_kernel,
                       cudaFuncAttributeMaxDynamicSharedMemorySize,
                       ATT_SMEM_BYTES);

  dim3 gg(CC / 128, MALL / 128);  // (8, 32)
  sgemm_tf32_kernel<<<gg, 256>>>(xq, Wq, bq, q);
  sgemm_tf32_kernel<<<gg, 256>>>(xkv, Wk, bk, k);
  sgemm_tf32_kernel<<<gg, 256>>>(xkv, Wv, bv, v);
  attn_tf32_kernel<<<dim3(NN / 128, BB * HH), 512, ATT_SMEM_BYTES>>>(q, k, v,
                                                                     att);
  sgemm_tf32_kernel<<<gg, 256>>>(att, Wo, bo, out);
}

// round 5
// speedup vs baseline: 1.4746x; 1.4746x over previous
#include <cuda_runtime.h>
#include <cuda_fp16.h>
#include <math.h>

constexpr int BB = 2;
constexpr int NN = 2048;
constexpr int CC = 1024;
constexpr int HH = 8;
constexpr int DH = 128;
constexpr int MALL = BB * NN;  // 4096

__device__ float g_q[(size_t)MALL * CC];
__device__ float g_k[(size_t)MALL * CC];
__device__ float g_v[(size_t)MALL * CC];
__device__ float g_att[(size_t)MALL * CC];

// ---------------------------------------------------------------------------
// helpers
// ---------------------------------------------------------------------------
__device__ __forceinline__ float f2tf(float x) {
  unsigned u;
  asm("cvt.rna.tf32.f32 %0, %1;" : "=r"(u) : "f"(x));
  return __uint_as_float(u);
}
__device__ __forceinline__ unsigned fu(float x) { return __float_as_uint(x); }

// tf32: D += A(16x8) * B(8x8)
__device__ __forceinline__ void mma8(float* c, const unsigned* a, unsigned b0,
                                     unsigned b1) {
  asm volatile(
      "mma.sync.aligned.m16n8k8.row.col.f32.tf32.tf32.f32 "
      "{%0,%1,%2,%3}, {%4,%5,%6,%7}, {%8,%9}, {%0,%1,%2,%3};"
      : "+f"(c[0]), "+f"(c[1]), "+f"(c[2]), "+f"(c[3])
      : "r"(a[0]), "r"(a[1]), "r"(a[2]), "r"(a[3]), "r"(b0), "r"(b1));
}

// fp16: D += A(16x16) * B(16x8), fp32 accum
__device__ __forceinline__ void hmma16(float* c, const unsigned* a, unsigned b0,
                                       unsigned b1) {
  asm volatile(
      "mma.sync.aligned.m16n8k16.row.col.f32.f16.f16.f32 "
      "{%0,%1,%2,%3}, {%4,%5,%6,%7}, {%8,%9}, {%0,%1,%2,%3};"
      : "+f"(c[0]), "+f"(c[1]), "+f"(c[2]), "+f"(c[3])
      : "r"(a[0]), "r"(a[1]), "r"(a[2]), "r"(a[3]), "r"(b0), "r"(b1));
}

__device__ __forceinline__ unsigned h2u(__half2 h) {
  return *reinterpret_cast<unsigned*>(&h);
}

// ---------------------------------------------------------------------------
// GEMM: C[4096,1024] = A @ B + bias, tf32 tensor-core (unchanged, known-good)
// ---------------------------------------------------------------------------
__global__ __launch_bounds__(256) void sgemm_tf32_kernel(
    const float* __restrict__ A, const float* __restrict__ B,
    const float* __restrict__ bias, float* __restrict__ C) {
  constexpr int K = 1024, N = 1024;
  __shared__ float As[128][36];
  __shared__ float Bs[32][136];

  const int tid = threadIdx.x;
  const int warp = tid >> 5, lane = tid & 31;
  const int g = lane >> 2, t = lane & 3;
  const int wm = warp & 3, wn = warp >> 2;
  const int bx = blockIdx.x, by = blockIdx.y;

  const int ar = tid >> 3, ac = (tid & 7) * 4;
  const int bkr = tid >> 5, bc = (tid & 31) * 4;

  float acc[2][8][4];
#pragma unroll
  for (int mt = 0; mt < 2; mt++)
#pragma unroll
    for (int nt = 0; nt < 8; nt++)
#pragma unroll
      for (int i = 0; i < 4; i++) acc[mt][nt][i] = 0.f;

  float4 pa[4], pb[4];
#pragma unroll
  for (int i = 0; i < 4; i++) {
    pa[i] = *(const float4*)(A + (size_t)(by * 128 + ar + 32 * i) * K + ac);
    pb[i] = *(const float4*)(B + (size_t)(bkr + 8 * i) * N + bx * 128 + bc);
  }

  for (int k0 = 0; k0 < K; k0 += 32) {
#pragma unroll
    for (int i = 0; i < 4; i++) {
      As[ar + 32 * i][ac + 0] = f2tf(pa[i].x);
      As[ar + 32 * i][ac + 1] = f2tf(pa[i].y);
      As[ar + 32 * i][ac + 2] = f2tf(pa[i].z);
      As[ar + 32 * i][ac + 3] = f2tf(pa[i].w);
      Bs[bkr + 8 * i][bc + 0] = f2tf(pb[i].x);
      Bs[bkr + 8 * i][bc + 1] = f2tf(pb[i].y);
      Bs[bkr + 8 * i][bc + 2] = f2tf(pb[i].z);
      Bs[bkr + 8 * i][bc + 3] = f2tf(pb[i].w);
    }
    __syncthreads();

    if (k0 + 32 < K) {
#pragma unroll
      for (int i = 0; i < 4; i++) {
        pa[i] = *(const float4*)(A + (size_t)(by * 128 + ar + 32 * i) * K +
                                 k0 + 32 + ac);
        pb[i] = *(const float4*)(B + (size_t)(k0 + 32 + bkr + 8 * i) * N +
                                 bx * 128 + bc);
      }
    }

#pragma unroll
    for (int ks = 0; ks < 4; ks++) {
      const int kk = ks * 8;
      unsigned afr[2][4];
#pragma unroll
      for (int mt = 0; mt < 2; mt++) {
        const int rr = wm * 32 + mt * 16;
        afr[mt][0] = fu(As[rr + g][kk + t]);
        afr[mt][1] = fu(As[rr + g + 8][kk + t]);
        afr[mt][2] = fu(As[rr + g][kk + t + 4]);
        afr[mt][3] = fu(As[rr + g + 8][kk + t + 4]);
      }
#pragma unroll
      for (int nt = 0; nt < 8; nt++) {
        const int cc = wn * 64 + nt * 8 + g;
        unsigned b0 = fu(Bs[kk + t][cc]);
        unsigned b1 = fu(Bs[kk + t + 4][cc]);
        mma8(acc[0][nt], afr[0], b0, b1);
        mma8(acc[1][nt], afr[1], b0, b1);
      }
    }
    __syncthreads();
  }

#pragma unroll
  for (int mt = 0; mt < 2; mt++) {
    const int r0 = by * 128 + wm * 32 + mt * 16 + g;
#pragma unroll
    for (int nt = 0; nt < 8; nt++) {
      const int c = bx * 128 + wn * 64 + nt * 8 + 2 * t;
      const float bx0 = bias[c], bx1 = bias[c + 1];
      float2 o0 = {acc[mt][nt][0] + bx0, acc[mt][nt][1] + bx1};
      float2 o1 = {acc[mt][nt][2] + bx0, acc[mt][nt][3] + bx1};
      *(float2*)(C + (size_t)r0 * N + c) = o0;
      *(float2*)(C + (size_t)(r0 + 8) * N + c) = o1;
    }
  }
}

// ---------------------------------------------------------------------------
// Flash attention, fp16 mma / fp32 accum, register-resident softmax.
// 256 threads / 8 warps. Br=128 (16 rows per warp, full 64-col S in regs),
// Bc=64.
// smem (half2 units): sQ[128][68], sK[64][68], sV = half[64][132]
// ---------------------------------------------------------------------------
constexpr int Q2_STR = 68;   // half2 stride (== 4 mod 32 -> bank 4g+t)
constexpr int V_STR = 132;   // half stride
constexpr int OQ2 = 0;
constexpr int OK2 = 128 * Q2_STR;         // 8704
constexpr int OV2 = OK2 + 64 * Q2_STR;    // 13056
constexpr int ATT_SMEM_BYTES = (OV2 + 64 * V_STR / 2) * 4;  // 69,120 B

__global__ __launch_bounds__(256) void attn_fp16_kernel(
    const float* __restrict__ Q, const float* __restrict__ K,
    const float* __restrict__ V, float* __restrict__ O) {
  extern __shared__ __half2 sm2[];
  __half* sVh = reinterpret_cast<__half*>(sm2 + OV2);
  __half2* sV2 = sm2 + OV2;

  const int tid = threadIdx.x;
  const int warp = tid >> 5, lane = tid & 31;
  const int g = lane >> 2, t = lane & 3;
  const int rr = warp * 16;  // 8 warps x 16 rows = Br 128
  const int bh = blockIdx.y;
  const int b = bh >> 3, h = bh & 7;
  const int n0 = blockIdx.x * 128;

  const float* Qb = Q + (size_t)b * NN * CC + (size_t)h * DH;
  const float* Kb = K + (size_t)b * NN * CC + (size_t)h * DH;
  const float* Vb = V + (size_t)b * NN * CC + (size_t)h * DH;
  const float scale = 0.08838834764831845f;  // 1/sqrt(128)

  // ---- load Q tile (scaled, fp16) : 128 rows x 32 float4 ----
#pragma unroll
  for (int i = 0; i < 16; i++) {
    int l = tid + 256 * i;
    int r = l >> 5, d4 = (l & 31) << 2;
    float4 q = *(const float4*)(Qb + (size_t)(n0 + r) * CC + d4);
    sm2[r * Q2_STR + (d4 >> 1)] = __floats2half2_rn(q.x * scale, q.y * scale);
    sm2[r * Q2_STR + (d4 >> 1) + 1] =
        __floats2half2_rn(q.z * scale, q.w * scale);
  }

  float m0 = -INFINITY, m1 = -INFINITY, l0 = 0.f, l1 = 0.f;
  float oacc[16][4];
#pragma unroll
  for (int nt = 0; nt < 16; nt++)
#pragma unroll
    for (int i = 0; i < 4; i++) oacc[nt][i] = 0.f;
  __syncthreads();

  for (int j0 = 0; j0 < NN; j0 += 64) {
    // ---- load K (half2 rows) and V (half rows) ----
#pragma unroll
    for (int i = 0; i < 8; i++) {
      int l = tid + 256 * i;
      int r = l >> 5, d4 = (l & 31) << 2;
      float4 kq = *(const float4*)(Kb + (size_t)(j0 + r) * CC + d4);
      sm2[OK2 + r * Q2_STR + (d4 >> 1)] = __floats2half2_rn(kq.x, kq.y);
      sm2[OK2 + r * Q2_STR + (d4 >> 1) + 1] = __floats2half2_rn(kq.z, kq.w);
      float4 vv = *(const float4*)(Vb + (size_t)(j0 + r) * CC + d4);
      sV2[(r * V_STR + d4) >> 1] = __floats2half2_rn(vv.x, vv.y);
      sV2[((r * V_STR + d4) >> 1) + 1] = __floats2half2_rn(vv.z, vv.w);
    }
    __syncthreads();

    // ---- S = Q @ K^T : 16 rows x 64 cols per warp, 8 k16 steps ----
    float sacc[8][4];
#pragma unroll
    for (int nt = 0; nt < 8; nt++)
#pragma unroll
      for (int i = 0; i < 4; i++) sacc[nt][i] = 0.f;

#pragma unroll
    for (int ks = 0; ks < 8; ks++) {
      const int kb = ks * 8;  // half2 index
      unsigned a[4];
      a[0] = *(const unsigned*)(sm2 + (rr + g) * Q2_STR + kb + t);
      a[1] = *(const unsigned*)(sm2 + (rr + g + 8) * Q2_STR + kb + t);
      a[2] = *(const unsigned*)(sm2 + (rr + g) * Q2_STR + kb + t + 4);
      a[3] = *(const unsigned*)(sm2 + (rr + g + 8) * Q2_STR + kb + t + 4);
#pragma unroll
      for (int nt = 0; nt < 8; nt++) {
        const int cc = nt * 8 + g;
        unsigned b0 = *(const unsigned*)(sm2 + OK2 + cc * Q2_STR + kb + t);
        unsigned b1 = *(const unsigned*)(sm2 + OK2 + cc * Q2_STR + kb + t + 4);
        hmma16(sacc[nt], a, b0, b1);
      }
    }

    // ---- register softmax: row g (c0,c1), row g+8 (c2,c3) ----
    float mx0 = -INFINITY, mx1 = -INFINITY;
#pragma unroll
    for (int nt = 0; nt < 8; nt++) {
      mx0 = fmaxf(mx0, fmaxf(sacc[nt][0], sacc[nt][1]));
      mx1 = fmaxf(mx1, fmaxf(sacc[nt][2], sacc[nt][3]));
    }
    mx0 = fmaxf(mx0, __shfl_xor_sync(0xffffffffu, mx0, 1));
    mx0 = fmaxf(mx0, __shfl_xor_sync(0xffffffffu, mx0, 2));
    mx1 = fmaxf(mx1, __shfl_xor_sync(0xffffffffu, mx1, 1));
    mx1 = fmaxf(mx1, __shfl_xor_sync(0xffffffffu, mx1, 2));

    const float mn0 = fmaxf(m0, mx0), mn1 = fmaxf(m1, mx1);
    const float al0 = __expf(m0 - mn0), al1 = __expf(m1 - mn1);
    m0 = mn0;
    m1 = mn1;

    __half2 pa[8], pb[8];
    float s0 = 0.f, s1 = 0.f;
#pragma unroll
    for (int nt = 0; nt < 8; nt++) {
      pa[nt] = __floats2half2_rn(__expf(sacc[nt][0] - mn0),
                                 __expf(sacc[nt][1] - mn0));
      pb[nt] = __floats2half2_rn(__expf(sacc[nt][2] - mn1),
                                 __expf(sacc[nt][3] - mn1));
      float2 fa = __half22float2(pa[nt]);
      float2 fb = __half22float2(pb[nt]);
      s0 += fa.x + fa.y;   // L from rounded P -> matches PV numerator
      s1 += fb.x + fb.y;
    }
    s0 += __shfl_xor_sync(0xffffffffu, s0, 1);
    s0 += __shfl_xor_sync(0xffffffffu, s0, 2);
    s1 += __shfl_xor_sync(0xffffffffu, s1, 1);
    s1 += __shfl_xor_sync(0xffffffffu, s1, 2);
    l0 = l0 * al0 + s0;
    l1 = l1 * al1 + s1;

#pragma unroll
    for (int nt = 0; nt < 16; nt++) {
      oacc[nt][0] *= al0;
      oacc[nt][1] *= al0;
      oacc[nt][2] *= al1;
      oacc[nt][3] *= al1;
    }

    // ---- PV: O += P @ V : 16 rows x 128 cols per warp, 4 k16 steps ----
#pragma unroll
    for (int ks = 0; ks < 4; ks++) {
      unsigned a[4];
      a[0] = h2u(pa[2 * ks]);
      a[1] = h2u(pb[2 * ks]);
      a[2] = h2u(pa[2 * ks + 1]);
      a[3] = h2u(pb[2 * ks + 1]);
      const int r0 = ks * 16 + 2 * t;
#pragma unroll
      for (int nt = 0; nt < 16; nt++) {
        const int cc = nt * 8 + g;
        unsigned v00 = *(const unsigned short*)(sVh + r0 * V_STR + cc);
        unsigned v01 = *(const unsigned short*)(sVh + (r0 + 1) * V_STR + cc);
        unsigned v10 = *(const unsigned short*)(sVh + (r0 + 8) * V_STR + cc);
        unsigned v11 = *(const unsigned short*)(sVh + (r0 + 9) * V_STR + cc);
        unsigned b0 = v00 | (v01 << 16);
        unsigned b1 = v10 | (v11 << 16);
        hmma16(oacc[nt], a, b0, b1);
      }
    }
    __syncthreads();
  }

  // ---- epilogue: O = oacc / l ----
  float* Ob = O + (size_t)b * NN * CC + (size_t)h * DH;
  const float inv0 = 1.0f / l0, inv1 = 1.0f / l1;
  const int row = n0 + rr + g;
#pragma unroll
  for (int nt = 0; nt < 16; nt++) {
    const int c = nt * 8 + 2 * t;
    *(float2*)(Ob + (size_t)row * CC + c) =
        make_float2(oacc[nt][0] * inv0, oacc[nt][1] * inv0);
    *(float2*)(Ob + (size_t)(row + 8) * CC + c) =
        make_float2(oacc[nt][2] * inv1, oacc[nt][3] * inv1);
  }
}

// ---------------------------------------------------------------------------
extern "C" void kernel_launch(void* const* d_in, const int* in_sizes, int n_in,
                              void* d_out, int out_size) {
  const float* xq = (const float*)d_in[0];
  const float* xkv = (const float*)d_in[1];
  const float* Wq = (const float*)d_in[2];
  const float* bq = (const float*)d_in[3];
  const float* Wk = (const float*)d_in[4];
  const float* bk = (const float*)d_in[5];
  const float* Wv = (const float*)d_in[6];
  const float* bv = (const float*)d_in[7];
  const float* Wo = (const float*)d_in[8];
  const float* bo = (const float*)d_in[9];
  float* out = (float*)d_out;

  float *q, *k, *v, *att;
  cudaGetSymbolAddress((void**)&q, g_q);
  cudaGetSymbolAddress((void**)&k, g_k);
  cudaGetSymbolAddress((void**)&v, g_v);
  cudaGetSymbolAddress((void**)&att, g_att);

  cudaFuncSetAttribute(attn_fp16_kernel,
                       cudaFuncAttributeMaxDynamicSharedMemorySize,
                       ATT_SMEM_BYTES);

  dim3 gg(CC / 128, MALL / 128);  // (8, 32)
  sgemm_tf32_kernel<<<gg, 256>>>(xq, Wq, bq, q);
  sgemm_tf32_kernel<<<gg, 256>>>(xkv, Wk, bk, k);
  sgemm_tf32_kernel<<<gg, 256>>>(xkv, Wv, bv, v);
  attn_fp16_kernel<<<dim3(NN / 128, BB * HH), 256, ATT_SMEM_BYTES>>>(q, k, v,
                                                                     att);
  sgemm_tf32_kernel<<<gg, 256>>>(att, Wo, bo, out);
}

// round 6
// speedup vs baseline: 1.7639x; 1.1962x over previous
#include <cuda_runtime.h>
#include <cuda_fp16.h>
#include <math.h>

constexpr int BB = 2;
constexpr int NN = 2048;
constexpr int CC = 1024;
constexpr int HH = 8;
constexpr int DH = 128;
constexpr int MALL = BB * NN;  // 4096

__device__ float g_q[(size_t)MALL * CC];
__device__ float g_k[(size_t)MALL * CC];
__device__ float g_v[(size_t)MALL * CC];
__device__ float g_att[(size_t)MALL * CC];
__device__ __half g_wt[4ull * CC * CC];  // W^T, fp16, [4][n][k]

// ---------------------------------------------------------------------------
// helpers
// ---------------------------------------------------------------------------
__device__ __forceinline__ unsigned h2u(__half2 h) {
  return *reinterpret_cast<unsigned*>(&h);
}

// fp16: D += A(16x16) * B(16x8), fp32 accum
__device__ __forceinline__ void hmma16(float* c, const unsigned* a, unsigned b0,
                                       unsigned b1) {
  asm volatile(
      "mma.sync.aligned.m16n8k16.row.col.f32.f16.f16.f32 "
      "{%0,%1,%2,%3}, {%4,%5,%6,%7}, {%8,%9}, {%0,%1,%2,%3};"
      : "+f"(c[0]), "+f"(c[1]), "+f"(c[2]), "+f"(c[3])
      : "r"(a[0]), "r"(a[1]), "r"(a[2]), "r"(a[3]), "r"(b0), "r"(b1));
}

// ---------------------------------------------------------------------------
// Transpose + fp16 convert: Wt[z][n][k] = (half)W_z[k][n], 1024x1024 each.
// ---------------------------------------------------------------------------
__global__ __launch_bounds__(256) void transpose_h_kernel(
    const float* __restrict__ W0, const float* __restrict__ W1,
    const float* __restrict__ W2, const float* __restrict__ W3,
    __half* __restrict__ out) {
  __shared__ float tile[32][33];
  const float* W = (blockIdx.z == 0) ? W0
                   : (blockIdx.z == 1) ? W1
                   : (blockIdx.z == 2) ? W2 : W3;
  __half* o = out + (size_t)blockIdx.z * CC * CC;
  const int k0 = blockIdx.y * 32, n0 = blockIdx.x * 32;
  const int tx = threadIdx.x & 31, ty = threadIdx.x >> 5;
#pragma unroll
  for (int i = 0; i < 32; i += 8)
    tile[ty + i][tx] = W[(size_t)(k0 + ty + i) * CC + n0 + tx];
  __syncthreads();
#pragma unroll
  for (int i = 0; i < 32; i += 8)
    o[(size_t)(n0 + ty + i) * CC + k0 + tx] = __float2half(tile[tx][ty + i]);
}

// ---------------------------------------------------------------------------
// fp16 GEMM: C[4096,1024] = A @ B + bias.  A fp32 [M][K]; Bt fp16 [N][K].
// 128x128x32 tiles, 8 warps (4m x 2n), warp tile 32x64, m16n8k16.
// smem half2 stride 20 (== 20 mod 32): frag bank = 20g+t, conflict-free.
// ---------------------------------------------------------------------------
constexpr int GST2 = 20;  // half2 words per row (16 data + 4 pad)

__global__ __launch_bounds__(256) void hgemm_kernel(
    const float* __restrict__ A, const __half* __restrict__ Bt,
    const float* __restrict__ bias, float* __restrict__ C) {
  constexpr int K = 1024, N = 1024;
  __shared__ __half2 sA[128 * GST2];
  __shared__ __half2 sB[128 * GST2];

  const int tid = threadIdx.x;
  const int warp = tid >> 5, lane = tid & 31;
  const int g = lane >> 2, t = lane & 3;
  const int wm = warp & 3, wn = warp >> 2;
  const int bx = blockIdx.x, by = blockIdx.y;

  const int ar = tid >> 3, ac = (tid & 7) * 4;  // A: rows ar+32i, float col ac
  const int br = tid >> 2, bcw = (tid & 3) * 4; // B: rows br+64i, half2 word bcw

  float acc[2][8][4];
#pragma unroll
  for (int mt = 0; mt < 2; mt++)
#pragma unroll
    for (int nt = 0; nt < 8; nt++)
#pragma unroll
      for (int i = 0; i < 4; i++) acc[mt][nt][i] = 0.f;

  float4 pa[4];
  uint4 pb[2];
#pragma unroll
  for (int i = 0; i < 4; i++)
    pa[i] = *(const float4*)(A + (size_t)(by * 128 + ar + 32 * i) * K + ac);
#pragma unroll
  for (int i = 0; i < 2; i++)
    pb[i] = *(const uint4*)(Bt + (size_t)(bx * 128 + br + 64 * i) * K +
                            bcw * 2);

  for (int k0 = 0; k0 < K; k0 += 32) {
#pragma unroll
    for (int i = 0; i < 4; i++) {
      const int r = ar + 32 * i;
      sA[r * GST2 + (ac >> 1)] = __floats2half2_rn(pa[i].x, pa[i].y);
      sA[r * GST2 + (ac >> 1) + 1] = __floats2half2_rn(pa[i].z, pa[i].w);
    }
#pragma unroll
    for (int i = 0; i < 2; i++)
      *(uint4*)&sB[(br + 64 * i) * GST2 + bcw] = pb[i];
    __syncthreads();

    if (k0 + 32 < K) {
#pragma unroll
      for (int i = 0; i < 4; i++)
        pa[i] = *(const float4*)(A + (size_t)(by * 128 + ar + 32 * i) * K +
                                 k0 + 32 + ac);
#pragma unroll
      for (int i = 0; i < 2; i++)
        pb[i] = *(const uint4*)(Bt + (size_t)(bx * 128 + br + 64 * i) * K +
                                k0 + 32 + bcw * 2);
    }

#pragma unroll
    for (int ks = 0; ks < 2; ks++) {
      const int kb = ks * 8;
      unsigned a[2][4];
#pragma unroll
      for (int mt = 0; mt < 2; mt++) {
        const int rr = wm * 32 + mt * 16;
        a[mt][0] = h2u(sA[(rr + g) * GST2 + kb + t]);
        a[mt][1] = h2u(sA[(rr + g + 8) * GST2 + kb + t]);
        a[mt][2] = h2u(sA[(rr + g) * GST2 + kb + t + 4]);
        a[mt][3] = h2u(sA[(rr + g + 8) * GST2 + kb + t + 4]);
      }
#pragma unroll
      for (int nt = 0; nt < 8; nt++) {
        const int cc = wn * 64 + nt * 8 + g;
        unsigned b0 = h2u(sB[cc * GST2 + kb + t]);
        unsigned b1 = h2u(sB[cc * GST2 + kb + t + 4]);
        hmma16(acc[0][nt], a[0], b0, b1);
        hmma16(acc[1][nt], a[1], b0, b1);
      }
    }
    __syncthreads();
  }

#pragma unroll
  for (int mt = 0; mt < 2; mt++) {
    const int r0 = by * 128 + wm * 32 + mt * 16 + g;
#pragma unroll
    for (int nt = 0; nt < 8; nt++) {
      const int c = bx * 128 + wn * 64 + nt * 8 + 2 * t;
      const float bx0 = bias[c], bx1 = bias[c + 1];
      float2 o0 = {acc[mt][nt][0] + bx0, acc[mt][nt][1] + bx1};
      float2 o1 = {acc[mt][nt][2] + bx0, acc[mt][nt][3] + bx1};
      *(float2*)(C + (size_t)r0 * N + c) = o0;
      *(float2*)(C + (size_t)(r0 + 8) * N + c) = o1;
    }
  }
}

// ---------------------------------------------------------------------------
// Flash attention, fp16 mma / fp32 accum, register-resident softmax.
// (unchanged from round 5 — verified at 216 us)
// ---------------------------------------------------------------------------
constexpr int Q2_STR = 68;
constexpr int V_STR = 132;
constexpr int OK2 = 128 * Q2_STR;
constexpr int OV2 = OK2 + 64 * Q2_STR;
constexpr int ATT_SMEM_BYTES = (OV2 + 64 * V_STR / 2) * 4;  // 69,120 B

__global__ __launch_bounds__(256) void attn_fp16_kernel(
    const float* __restrict__ Q, const float* __restrict__ K,
    const float* __restrict__ V, float* __restrict__ O) {
  extern __shared__ __half2 sm2[];
  __half* sVh = reinterpret_cast<__half*>(sm2 + OV2);
  __half2* sV2 = sm2 + OV2;

  const int tid = threadIdx.x;
  const int warp = tid >> 5, lane = tid & 31;
  const int g = lane >> 2, t = lane & 3;
  const int rr = warp * 16;
  const int bh = blockIdx.y;
  const int b = bh >> 3, h = bh & 7;
  const int n0 = blockIdx.x * 128;

  const float* Qb = Q + (size_t)b * NN * CC + (size_t)h * DH;
  const float* Kb = K + (size_t)b * NN * CC + (size_t)h * DH;
  const float* Vb = V + (size_t)b * NN * CC + (size_t)h * DH;
  const float scale = 0.08838834764831845f;

#pragma unroll
  for (int i = 0; i < 16; i++) {
    int l = tid + 256 * i;
    int r = l >> 5, d4 = (l & 31) << 2;
    float4 q = *(const float4*)(Qb + (size_t)(n0 + r) * CC + d4);
    sm2[r * Q2_STR + (d4 >> 1)] = __floats2half2_rn(q.x * scale, q.y * scale);
    sm2[r * Q2_STR + (d4 >> 1) + 1] =
        __floats2half2_rn(q.z * scale, q.w * scale);
  }

  float m0 = -INFINITY, m1 = -INFINITY, l0 = 0.f, l1 = 0.f;
  float oacc[16][4];
#pragma unroll
  for (int nt = 0; nt < 16; nt++)
#pragma unroll
    for (int i = 0; i < 4; i++) oacc[nt][i] = 0.f;
  __syncthreads();

  for (int j0 = 0; j0 < NN; j0 += 64) {
#pragma unroll
    for (int i = 0; i < 8; i++) {
      int l = tid + 256 * i;
      int r = l >> 5, d4 = (l & 31) << 2;
      float4 kq = *(const float4*)(Kb + (size_t)(j0 + r) * CC + d4);
      sm2[OK2 + r * Q2_STR + (d4 >> 1)] = __floats2half2_rn(kq.x, kq.y);
      sm2[OK2 + r * Q2_STR + (d4 >> 1) + 1] = __floats2half2_rn(kq.z, kq.w);
      float4 vv = *(const float4*)(Vb + (size_t)(j0 + r) * CC + d4);
      sV2[(r * V_STR + d4) >> 1] = __floats2half2_rn(vv.x, vv.y);
      sV2[((r * V_STR + d4) >> 1) + 1] = __floats2half2_rn(vv.z, vv.w);
    }
    __syncthreads();

    float sacc[8][4];
#pragma unroll
    for (int nt = 0; nt < 8; nt++)
#pragma unroll
      for (int i = 0; i < 4; i++) sacc[nt][i] = 0.f;

#pragma unroll
    for (int ks = 0; ks < 8; ks++) {
      const int kb = ks * 8;
      unsigned a[4];
      a[0] = h2u(sm2[(rr + g) * Q2_STR + kb + t]);
      a[1] = h2u(sm2[(rr + g + 8) * Q2_STR + kb + t]);
      a[2] = h2u(sm2[(rr + g) * Q2_STR + kb + t + 4]);
      a[3] = h2u(sm2[(rr + g + 8) * Q2_STR + kb + t + 4]);
#pragma unroll
      for (int nt = 0; nt < 8; nt++) {
        const int cc = nt * 8 + g;
        unsigned b0 = h2u(sm2[OK2 + cc * Q2_STR + kb + t]);
        unsigned b1 = h2u(sm2[OK2 + cc * Q2_STR + kb + t + 4]);
        hmma16(sacc[nt], a, b0, b1);
      }
    }

    float mx0 = -INFINITY, mx1 = -INFINITY;
#pragma unroll
    for (int nt = 0; nt < 8; nt++) {
      mx0 = fmaxf(mx0, fmaxf(sacc[nt][0], sacc[nt][1]));
      mx1 = fmaxf(mx1, fmaxf(sacc[nt][2], sacc[nt][3]));
    }
    mx0 = fmaxf(mx0, __shfl_xor_sync(0xffffffffu, mx0, 1));
    mx0 = fmaxf(mx0, __shfl_xor_sync(0xffffffffu, mx0, 2));
    mx1 = fmaxf(mx1, __shfl_xor_sync(0xffffffffu, mx1, 1));
    mx1 = fmaxf(mx1, __shfl_xor_sync(0xffffffffu, mx1, 2));

    const float mn0 = fmaxf(m0, mx0), mn1 = fmaxf(m1, mx1);
    const float al0 = __expf(m0 - mn0), al1 = __expf(m1 - mn1);
    m0 = mn0;
    m1 = mn1;

    __half2 pa[8], pb[8];
    float s0 = 0.f, s1 = 0.f;
#pragma unroll
    for (int nt = 0; nt < 8; nt++) {
      pa[nt] = __floats2half2_rn(__expf(sacc[nt][0] - mn0),
                                 __expf(sacc[nt][1] - mn0));
      pb[nt] = __floats2half2_rn(__expf(sacc[nt][2] - mn1),
                                 __expf(sacc[nt][3] - mn1));
      float2 fa = __half22float2(pa[nt]);
      float2 fb = __half22float2(pb[nt]);
      s0 += fa.x + fa.y;
      s1 += fb.x + fb.y;
    }
    s0 += __shfl_xor_sync(0xffffffffu, s0, 1);
    s0 += __shfl_xor_sync(0xffffffffu, s0, 2);
    s1 += __shfl_xor_sync(0xffffffffu, s1, 1);
    s1 += __shfl_xor_sync(0xffffffffu, s1, 2);
    l0 = l0 * al0 + s0;
    l1 = l1 * al1 + s1;

#pragma unroll
    for (int nt = 0; nt < 16; nt++) {
      oacc[nt][0] *= al0;
      oacc[nt][1] *= al0;
      oacc[nt][2] *= al1;
      oacc[nt][3] *= al1;
    }

#pragma unroll
    for (int ks = 0; ks < 4; ks++) {
      unsigned a[4];
      a[0] = h2u(pa[2 * ks]);
      a[1] = h2u(pb[2 * ks]);
      a[2] = h2u(pa[2 * ks + 1]);
      a[3] = h2u(pb[2 * ks + 1]);
      const int r0 = ks * 16 + 2 * t;
#pragma unroll
      for (int nt = 0; nt < 16; nt++) {
        const int cc = nt * 8 + g;
        unsigned v00 = *(const unsigned short*)(sVh + r0 * V_STR + cc);
        unsigned v01 = *(const unsigned short*)(sVh + (r0 + 1) * V_STR + cc);
        unsigned v10 = *(const unsigned short*)(sVh + (r0 + 8) * V_STR + cc);
        unsigned v11 = *(const unsigned short*)(sVh + (r0 + 9) * V_STR + cc);
        unsigned b0 = v00 | (v01 << 16);
        unsigned b1 = v10 | (v11 << 16);
        hmma16(oacc[nt], a, b0, b1);
      }
    }
    __syncthreads();
  }

  float* Ob = O + (size_t)b * NN * CC + (size_t)h * DH;
  const float inv0 = 1.0f / l0, inv1 = 1.0f / l1;
  const int row = n0 + rr + g;
#pragma unroll
  for (int nt = 0; nt < 16; nt++) {
    const int c = nt * 8 + 2 * t;
    *(float2*)(Ob + (size_t)row * CC + c) =
        make_float2(oacc[nt][0] * inv0, oacc[nt][1] * inv0);
    *(float2*)(Ob + (size_t)(row + 8) * CC + c) =
        make_float2(oacc[nt][2] * inv1, oacc[nt][3] * inv1);
  }
}

// ---------------------------------------------------------------------------
extern "C" void kernel_launch(void* const* d_in, const int* in_sizes, int n_in,
                              void* d_out, int out_size) {
  const float* xq = (const float*)d_in[0];
  const float* xkv = (const float*)d_in[1];
  const float* Wq = (const float*)d_in[2];
  const float* bq = (const float*)d_in[3];
  const float* Wk = (const float*)d_in[4];
  const float* bk = (const float*)d_in[5];
  const float* Wv = (const float*)d_in[6];
  const float* bv = (const float*)d_in[7];
  const float* Wo = (const float*)d_in[8];
  const float* bo = (const float*)d_in[9];
  float* out = (float*)d_out;

  float *q, *k, *v, *att;
  __half* wt;
  cudaGetSymbolAddress((void**)&q, g_q);
  cudaGetSymbolAddress((void**)&k, g_k);
  cudaGetSymbolAddress((void**)&v, g_v);
  cudaGetSymbolAddress((void**)&att, g_att);
  cudaGetSymbolAddress((void**)&wt, g_wt);

  cudaFuncSetAttribute(attn_fp16_kernel,
                       cudaFuncAttributeMaxDynamicSharedMemorySize,
                       ATT_SMEM_BYTES);

  const size_t WSZ = (size_t)CC * CC;
  transpose_h_kernel<<<dim3(32, 32, 4), 256>>>(Wq, Wk, Wv, Wo, wt);

  dim3 gg(CC / 128, MALL / 128);  // (8, 32)
  hgemm_kernel<<<gg, 256>>>(xq, wt + 0 * WSZ, bq, q);
  hgemm_kernel<<<gg, 256>>>(xkv, wt + 1 * WSZ, bk, k);
  hgemm_kernel<<<gg, 256>>>(xkv, wt + 2 * WSZ, bv, v);
  attn_fp16_kernel<<<dim3(NN / 128, BB * HH), 256, ATT_SMEM_BYTES>>>(q, k, v,
                                                                     att);
  hgemm_kernel<<<gg, 256>>>(att, wt + 3 * WSZ, bo, out);
}

// round 7
// speedup vs baseline: 1.8276x; 1.0361x over previous
#include <cuda_runtime.h>
#include <cuda_fp16.h>
#include <math.h>

constexpr int BB = 2;
constexpr int NN = 2048;
constexpr int CC = 1024;
constexpr int HH = 8;
constexpr int DH = 128;
constexpr int MALL = BB * NN;  // 4096

// fp16 intermediates (device globals: allocation-free per harness rules)
__device__ __half g_xqh[(size_t)MALL * CC];
__device__ __half g_xkvh[(size_t)MALL * CC];
__device__ __half g_qh[(size_t)MALL * CC];
__device__ __half g_kh[(size_t)MALL * CC];
__device__ __half g_vh[(size_t)MALL * CC];
__device__ __half g_atth[(size_t)MALL * CC];
__device__ __half g_wt[4ull * CC * CC];  // W^T fp16, [4][n][k]

// ---------------------------------------------------------------------------
// helpers
// ---------------------------------------------------------------------------
__device__ __forceinline__ unsigned h2u(__half2 h) {
  return *reinterpret_cast<unsigned*>(&h);
}

__device__ __forceinline__ void hmma16(float* c, const unsigned* a, unsigned b0,
                                       unsigned b1) {
  asm volatile(
      "mma.sync.aligned.m16n8k16.row.col.f32.f16.f16.f32 "
      "{%0,%1,%2,%3}, {%4,%5,%6,%7}, {%8,%9}, {%0,%1,%2,%3};"
      : "+f"(c[0]), "+f"(c[1]), "+f"(c[2]), "+f"(c[3])
      : "r"(a[0]), "r"(a[1]), "r"(a[2]), "r"(a[3]), "r"(b0), "r"(b1));
}

#define CP_ASYNC16(dst, src)                                        \
  asm volatile("cp.async.cg.shared.global [%0], [%1], 16;" ::"r"(dst), \
               "l"(src))
#define CP_COMMIT() asm volatile("cp.async.commit_group;")
#define CP_WAIT1() asm volatile("cp.async.wait_group 1;")

__device__ __forceinline__ void store2(float* p, float x, float y) {
  *(float2*)p = make_float2(x, y);
}
__device__ __forceinline__ void store2(__half* p, float x, float y) {
  *(__half2*)p = __floats2half2_rn(x, y);
}

// ---------------------------------------------------------------------------
// fp32 -> fp16 convert (x4 per thread)
// ---------------------------------------------------------------------------
__global__ __launch_bounds__(256) void f2h_kernel(const float* __restrict__ in,
                                                  __half* __restrict__ out) {
  const int i = blockIdx.x * 256 + threadIdx.x;
  float4 v = ((const float4*)in)[i];
  ((__half2*)out)[2 * i] = __floats2half2_rn(v.x, v.y);
  ((__half2*)out)[2 * i + 1] = __floats2half2_rn(v.z, v.w);
}

// ---------------------------------------------------------------------------
// Transpose + fp16 convert: Wt[z][n][k] = (half)W_z[k][n]
// ---------------------------------------------------------------------------
__global__ __launch_bounds__(256) void transpose_h_kernel(
    const float* __restrict__ W0, const float* __restrict__ W1,
    const float* __restrict__ W2, const float* __restrict__ W3,
    __half* __restrict__ out) {
  __shared__ float tile[32][33];
  const float* W = (blockIdx.z == 0) ? W0
                   : (blockIdx.z == 1) ? W1
                   : (blockIdx.z == 2) ? W2 : W3;
  __half* o = out + (size_t)blockIdx.z * CC * CC;
  const int k0 = blockIdx.y * 32, n0 = blockIdx.x * 32;
  const int tx = threadIdx.x & 31, ty = threadIdx.x >> 5;
#pragma unroll
  for (int i = 0; i < 32; i += 8)
    tile[ty + i][tx] = W[(size_t)(k0 + ty + i) * CC + n0 + tx];
  __syncthreads();
#pragma unroll
  for (int i = 0; i < 32; i += 8)
    o[(size_t)(n0 + ty + i) * CC + k0 + tx] = __float2half(tile[tx][ty + i]);
}

// ---------------------------------------------------------------------------
// fp16 GEMM with cp.async 3-stage pipeline.
// C[4096,1024] = A @ Bt^T + bias.  A half [M][K]; Bt half [N][K].
// 128x128x32 tiles, 8 warps (4m x 2n), warp tile 32x64, m16n8k16.
// smem half2 stride 20 (row = 80B, 16B-aligned; frag bank 20g+t cf-free).
// ---------------------------------------------------------------------------
constexpr int GST2 = 20;                 // half2 words per row
constexpr int GTILE = 128 * GST2;        // half2 words per tile
constexpr int GSTAGES = 3;
constexpr int GEMM_SMEM = GSTAGES * GTILE * 2 * 4;  // 61,440 B

template <typename OutT>
__global__ __launch_bounds__(256) void hgemm_cp_kernel(
    const __half* __restrict__ A, const __half* __restrict__ Bt,
    const float* __restrict__ bias, OutT* __restrict__ C) {
  constexpr int K = 1024, N = 1024;
  extern __shared__ __half2 dsm[];
  __half2* sA = dsm;
  __half2* sB = dsm + GSTAGES * GTILE;

  const int tid = threadIdx.x;
  const int warp = tid >> 5, lane = tid & 31;
  const int g = lane >> 2, t = lane & 3;
  const int wm = warp & 3, wn = warp >> 2;
  const int bx = blockIdx.x, by = blockIdx.y;

  const int cr = tid >> 1;          // copy row 0..127
  const int cw = (tid & 1) * 2;     // uint4 index {0,2}

  const __half* Ab = A + (size_t)(by * 128 + cr) * K + cw * 8;
  const __half* Bb = Bt + (size_t)(bx * 128 + cr) * K + cw * 8;

  const unsigned sa0 =
      (unsigned)__cvta_generic_to_shared(sA) + cr * (GST2 * 4) + cw * 16;
  const unsigned sb0 =
      (unsigned)__cvta_generic_to_shared(sB) + cr * (GST2 * 4) + cw * 16;

  float acc[2][8][4];
#pragma unroll
  for (int mt = 0; mt < 2; mt++)
#pragma unroll
    for (int nt = 0; nt < 8; nt++)
#pragma unroll
      for (int i = 0; i < 4; i++) acc[mt][nt][i] = 0.f;

  auto issue = [&](int stage, int k0) {
    const unsigned da = sa0 + stage * (GTILE * 4);
    const unsigned db = sb0 + stage * (GTILE * 4);
    CP_ASYNC16(da, Ab + k0);
    CP_ASYNC16(da + 16, Ab + k0 + 8);
    CP_ASYNC16(db, Bb + k0);
    CP_ASYNC16(db + 16, Bb + k0 + 8);
    CP_COMMIT();
  };

  issue(0, 0);
  issue(1, 32);

  for (int it = 0; it < K / 32; it++) {
    CP_WAIT1();
    __syncthreads();
    const int st = it % GSTAGES;
    const __half2* tA = sA + st * GTILE;
    const __half2* tB = sB + st * GTILE;

#pragma unroll
    for (int ks = 0; ks < 2; ks++) {
      const int kb = ks * 8;
      unsigned a[2][4];
#pragma unroll
      for (int mt = 0; mt < 2; mt++) {
        const int rr = wm * 32 + mt * 16;
        a[mt][0] = h2u(tA[(rr + g) * GST2 + kb + t]);
        a[mt][1] = h2u(tA[(rr + g + 8) * GST2 + kb + t]);
        a[mt][2] = h2u(tA[(rr + g) * GST2 + kb + t + 4]);
        a[mt][3] = h2u(tA[(rr + g + 8) * GST2 + kb + t + 4]);
      }
#pragma unroll
      for (int nt = 0; nt < 8; nt++) {
        const int cc = wn * 64 + nt * 8 + g;
        unsigned b0 = h2u(tB[cc * GST2 + kb + t]);
        unsigned b1 = h2u(tB[cc * GST2 + kb + t + 4]);
        hmma16(acc[0][nt], a[0], b0, b1);
        hmma16(acc[1][nt], a[1], b0, b1);
      }
    }
    if (it + 2 < K / 32) issue((it + 2) % GSTAGES, (it + 2) * 32);
    __syncthreads();
  }

#pragma unroll
  for (int mt = 0; mt < 2; mt++) {
    const int r0 = by * 128 + wm * 32 + mt * 16 + g;
#pragma unroll
    for (int nt = 0; nt < 8; nt++) {
      const int c = bx * 128 + wn * 64 + nt * 8 + 2 * t;
      const float bx0 = bias[c], bx1 = bias[c + 1];
      store2(C + (size_t)r0 * N + c, acc[mt][nt][0] + bx0,
             acc[mt][nt][1] + bx1);
      store2(C + (size_t)(r0 + 8) * N + c, acc[mt][nt][2] + bx0,
             acc[mt][nt][3] + bx1);
    }
  }
}

// ---------------------------------------------------------------------------
// Flash attention, fp16 in/out, fp16 mma / fp32 accum, register softmax.
// smem: sQ[128][68]h2, sK[64][68]h2, sV half[64][136]
// ---------------------------------------------------------------------------
constexpr int Q2_STR = 68;
constexpr int V_STR = 136;   // halves per row (272B, 16B-aligned)
constexpr int OK2 = 128 * Q2_STR;
constexpr int OV2 = OK2 + 64 * Q2_STR;             // 13056 half2 words
constexpr int ATT_SMEM_BYTES = (OV2 + 64 * V_STR / 2) * 4;  // 69,632 B

__global__ __launch_bounds__(256) void attn_fp16_kernel(
    const __half* __restrict__ Q, const __half* __restrict__ K,
    const __half* __restrict__ V, __half* __restrict__ O) {
  extern __shared__ __half2 sm2[];
  __half* sVh = reinterpret_cast<__half*>(sm2 + OV2);

  const int tid = threadIdx.x;
  const int warp = tid >> 5, lane = tid & 31;
  const int g = lane >> 2, t = lane & 3;
  const int rr = warp * 16;
  const int bh = blockIdx.y;
  const int b = bh >> 3, h = bh & 7;
  const int n0 = blockIdx.x * 128;

  const __half* Qb = Q + (size_t)b * NN * CC + (size_t)h * DH;
  const __half* Kb = K + (size_t)b * NN * CC + (size_t)h * DH;
  const __half* Vb = V + (size_t)b * NN * CC + (size_t)h * DH;
  const float scale = 0.08838834764831845f;  // applied to S in fp32

  // ---- Q tile: 128 rows x 16 uint4 (pure copy) ----
#pragma unroll
  for (int i = 0; i < 8; i++) {
    int l = tid + 256 * i;
    int r = l >> 4, w = l & 15;
    *(uint4*)(sm2 + r * Q2_STR + w * 4) =
        *(const uint4*)(Qb + (size_t)(n0 + r) * CC + w * 8);
  }

  float m0 = -INFINITY, m1 = -INFINITY, l0 = 0.f, l1 = 0.f;
  float oacc[16][4];
#pragma unroll
  for (int nt = 0; nt < 16; nt++)
#pragma unroll
    for (int i = 0; i < 4; i++) oacc[nt][i] = 0.f;
  __syncthreads();

  for (int j0 = 0; j0 < NN; j0 += 64) {
    // ---- K/V chunks: 64 rows x 16 uint4 each ----
#pragma unroll
    for (int i = 0; i < 4; i++) {
      int l = tid + 256 * i;
      int r = l >> 4, w = l & 15;
      *(uint4*)(sm2 + OK2 + r * Q2_STR + w * 4) =
          *(const uint4*)(Kb + (size_t)(j0 + r) * CC + w * 8);
      *(uint4*)(sVh + r * V_STR + w * 8) =
          *(const uint4*)(Vb + (size_t)(j0 + r) * CC + w * 8);
    }
    __syncthreads();

    // ---- S = Q @ K^T ----
    float sacc[8][4];
#pragma unroll
    for (int nt = 0; nt < 8; nt++)
#pragma unroll
      for (int i = 0; i < 4; i++) sacc[nt][i] = 0.f;

#pragma unroll
    for (int ks = 0; ks < 8; ks++) {
      const int kb = ks * 8;
      unsigned a[4];
      a[0] = h2u(sm2[(rr + g) * Q2_STR + kb + t]);
      a[1] = h2u(sm2[(rr + g + 8) * Q2_STR + kb + t]);
      a[2] = h2u(sm2[(rr + g) * Q2_STR + kb + t + 4]);
      a[3] = h2u(sm2[(rr + g + 8) * Q2_STR + kb + t + 4]);
#pragma unroll
      for (int nt = 0; nt < 8; nt++) {
        const int cc = nt * 8 + g;
        unsigned b0 = h2u(sm2[OK2 + cc * Q2_STR + kb + t]);
        unsigned b1 = h2u(sm2[OK2 + cc * Q2_STR + kb + t + 4]);
        hmma16(sacc[nt], a, b0, b1);
      }
    }
#pragma unroll
    for (int nt = 0; nt < 8; nt++)
#pragma unroll
      for (int i = 0; i < 4; i++) sacc[nt][i] *= scale;

    // ---- register softmax ----
    float mx0 = -INFINITY, mx1 = -INFINITY;
#pragma unroll
    for (int nt = 0; nt < 8; nt++) {
      mx0 = fmaxf(mx0, fmaxf(sacc[nt][0], sacc[nt][1]));
      mx1 = fmaxf(mx1, fmaxf(sacc[nt][2], sacc[nt][3]));
    }
    mx0 = fmaxf(mx0, __shfl_xor_sync(0xffffffffu, mx0, 1));
    mx0 = fmaxf(mx0, __shfl_xor_sync(0xffffffffu, mx0, 2));
    mx1 = fmaxf(mx1, __shfl_xor_sync(0xffffffffu, mx1, 1));
    mx1 = fmaxf(mx1, __shfl_xor_sync(0xffffffffu, mx1, 2));

    const float mn0 = fmaxf(m0, mx0), mn1 = fmaxf(m1, mx1);
    const float al0 = __expf(m0 - mn0), al1 = __expf(m1 - mn1);
    m0 = mn0;
    m1 = mn1;

    __half2 pa[8], pb[8];
    float s0 = 0.f, s1 = 0.f;
#pragma unroll
    for (int nt = 0; nt < 8; nt++) {
      pa[nt] = __floats2half2_rn(__expf(sacc[nt][0] - mn0),
                                 __expf(sacc[nt][1] - mn0));
      pb[nt] = __floats2half2_rn(__expf(sacc[nt][2] - mn1),
                                 __expf(sacc[nt][3] - mn1));
      float2 fa = __half22float2(pa[nt]);
      float2 fb = __half22float2(pb[nt]);
      s0 += fa.x + fa.y;  // L from rounded P -> matches PV numerator
      s1 += fb.x + fb.y;
    }
    s0 += __shfl_xor_sync(0xffffffffu, s0, 1);
    s0 += __shfl_xor_sync(0xffffffffu, s0, 2);
    s1 += __shfl_xor_sync(0xffffffffu, s1, 1);
    s1 += __shfl_xor_sync(0xffffffffu, s1, 2);
    l0 = l0 * al0 + s0;
    l1 = l1 * al1 + s1;

#pragma unroll
    for (int nt = 0; nt < 16; nt++) {
      oacc[nt][0] *= al0;
      oacc[nt][1] *= al0;
      oacc[nt][2] *= al1;
      oacc[nt][3] *= al1;
    }

    // ---- PV ----
#pragma unroll
    for (int ks = 0; ks < 4; ks++) {
      unsigned a[4];
      a[0] = h2u(pa[2 * ks]);
      a[1] = h2u(pb[2 * ks]);
      a[2] = h2u(pa[2 * ks + 1]);
      a[3] = h2u(pb[2 * ks + 1]);
      const int r0 = ks * 16 + 2 * t;
#pragma unroll
      for (int nt = 0; nt < 16; nt++) {
        const int cc = nt * 8 + g;
        unsigned v00 = *(const unsigned short*)(sVh + r0 * V_STR + cc);
        unsigned v01 = *(const unsigned short*)(sVh + (r0 + 1) * V_STR + cc);
        unsigned v10 = *(const unsigned short*)(sVh + (r0 + 8) * V_STR + cc);
        unsigned v11 = *(const unsigned short*)(sVh + (r0 + 9) * V_STR + cc);
        unsigned b0 = v00 | (v01 << 16);
        unsigned b1 = v10 | (v11 << 16);
        hmma16(oacc[nt], a, b0, b1);
      }
    }
    __syncthreads();
  }

  // ---- epilogue (half out) ----
  __half* Ob = O + (size_t)b * NN * CC + (size_t)h * DH;
  const float inv0 = 1.0f / l0, inv1 = 1.0f / l1;
  const int row = n0 + rr + g;
#pragma unroll
  for (int nt = 0; nt < 16; nt++) {
    const int c = nt * 8 + 2 * t;
    *(__half2*)(Ob + (size_t)row * CC + c) =
        __floats2half2_rn(oacc[nt][0] * inv0, oacc[nt][1] * inv0);
    *(__half2*)(Ob + (size_t)(row + 8) * CC + c) =
        __floats2half2_rn(oacc[nt][2] * inv1, oacc[nt][3] * inv1);
  }
}

// ---------------------------------------------------------------------------
extern "C" void kernel_launch(void* const* d_in, const int* in_sizes, int n_in,
                              void* d_out, int out_size) {
  const float* xq = (const float*)d_in[0];
  const float* xkv = (const float*)d_in[1];
  const float* Wq = (const float*)d_in[2];
  const float* bq = (const float*)d_in[3];
  const float* Wk = (const float*)d_in[4];
  const float* bk = (const float*)d_in[5];
  const float* Wv = (const float*)d_in[6];
  const float* bv = (const float*)d_in[7];
  const float* Wo = (const float*)d_in[8];
  const float* bo = (const float*)d_in[9];
  float* out = (float*)d_out;

  __half *xqh, *xkvh, *qh, *kh, *vh, *atth, *wt;
  cudaGetSymbolAddress((void**)&xqh, g_xqh);
  cudaGetSymbolAddress((void**)&xkvh, g_xkvh);
  cudaGetSymbolAddress((void**)&qh, g_qh);
  cudaGetSymbolAddress((void**)&kh, g_kh);
  cudaGetSymbolAddress((void**)&vh, g_vh);
  cudaGetSymbolAddress((void**)&atth, g_atth);
  cudaGetSymbolAddress((void**)&wt, g_wt);

  cudaFuncSetAttribute(attn_fp16_kernel,
                       cudaFuncAttributeMaxDynamicSharedMemorySize,
                       ATT_SMEM_BYTES);
  cudaFuncSetAttribute(hgemm_cp_kernel<__half>,
                       cudaFuncAttributeMaxDynamicSharedMemorySize, GEMM_SMEM);
  cudaFuncSetAttribute(hgemm_cp_kernel<float>,
                       cudaFuncAttributeMaxDynamicSharedMemorySize, GEMM_SMEM);

  const size_t WSZ = (size_t)CC * CC;
  const int CV_BLK = (MALL * CC / 4) / 256;  // 4096 blocks
  f2h_kernel<<<CV_BLK, 256>>>(xq, xqh);
  f2h_kernel<<<CV_BLK, 256>>>(xkv, xkvh);
  transpose_h_kernel<<<dim3(32, 32, 4), 256>>>(Wq, Wk, Wv, Wo, wt);

  dim3 gg(CC / 128, MALL / 128);  // (8, 32)
  hgemm_cp_kernel<__half><<<gg, 256, GEMM_SMEM>>>(xqh, wt + 0 * WSZ, bq, qh);
  hgemm_cp_kernel<__half><<<gg, 256, GEMM_SMEM>>>(xkvh, wt + 1 * WSZ, bk, kh);
  hgemm_cp_kernel<__half><<<gg, 256, GEMM_SMEM>>>(xkvh, wt + 2 * WSZ, bv, vh);
  attn_fp16_kernel<<<dim3(NN / 128, BB * HH), 256, ATT_SMEM_BYTES>>>(qh, kh,
                                                                     vh, atth);
  hgemm_cp_kernel<float><<<gg, 256, GEMM_SMEM>>>(atth, wt + 3 * WSZ, bo, out);
}